// round 9
// baseline (speedup 1.0000x reference)
#include <cuda_runtime.h>
#include <cuda_bf16.h>

// Problem constants
#define BB 4
#define CC 3
#define HW 45056          // 256*176 = 44*1024
#define SS 5
#define MM 18
#define SMN (SS*MM)       // 90
#define TILE 1024         // hw scalars per block tile
#define NTILES (HW/TILE)  // 44
#define NGROUP 10
#define SMG (SMN/NGROUP)  // 9  (s,m) tasks per block == warps per block
#define NWARP 9
#define THREADS (NWARP*32)       // 288
#define CHUNK 512                // floats per cp.async pipeline chunk
#define CHUNK4 (CHUNK/4)         // 128 float4
#define NCHUNK (TILE/CHUNK)      // 2 chunks per task (fills 2-stage ring)
#define NCOMP 16                 // 1 mask sum + 3 channels * 5 moments
#define TOTAL_BLOCKS (NTILES*BB*NGROUP)   // 1760

#define SMEM_TILE_F (6*TILE)              // 6144 floats (24KB): X'c0..2, Y'c0..2
#define SMEM_RING_F (NWARP*2*CHUNK)       // 9216 floats (36KB)
#define SMEM_TOTAL_B ((SMEM_TILE_F + SMEM_RING_F)*4)   // 61440 B

#define K1C 0.0001f       // (0.01)^2
#define K2C 0.0009f       // (0.03)^2
#define EPSF 1e-6f

// zero at module load; finalizing block re-zeroes after use so every
// kernel_launch / graph replay starts from zeros.
__device__ float g_part[BB * SMN * NCOMP];
__device__ unsigned int g_count;

// ---------- f32x2 packed math helpers (sm_103a) ----------
__device__ __forceinline__ unsigned long long pk2(float lo, float hi) {
    unsigned long long r;
    asm("mov.b64 %0, {%1, %2};" : "=l"(r) : "f"(lo), "f"(hi));
    return r;
}
__device__ __forceinline__ void upk2(unsigned long long v, float& lo, float& hi) {
    asm("mov.b64 {%0, %1}, %2;" : "=f"(lo), "=f"(hi) : "l"(v));
}
__device__ __forceinline__ unsigned long long mul2(unsigned long long a, unsigned long long b) {
    unsigned long long r;
    asm("mul.rn.f32x2 %0, %1, %2;" : "=l"(r) : "l"(a), "l"(b));
    return r;
}
__device__ __forceinline__ unsigned long long add2(unsigned long long a, unsigned long long b) {
    unsigned long long r;
    asm("add.rn.f32x2 %0, %1, %2;" : "=l"(r) : "l"(a), "l"(b));
    return r;
}
__device__ __forceinline__ unsigned long long fma2(unsigned long long a, unsigned long long b,
                                                   unsigned long long c) {
    unsigned long long r;
    asm("fma.rn.f32x2 %0, %1, %2, %3;" : "=l"(r) : "l"(a), "l"(b), "l"(c));
    return r;
}

// ---------- cp.async helpers ----------
// Copy one CHUNK (512 floats) warp-collectively: 4 x 16B per lane.
// Producer lane == consumer lane for every float4 (index j*32+lane), so no
// cross-lane sync is needed after cp.async.wait_group.
__device__ __forceinline__ void cp_chunk(float* dst, const float* src, int lane) {
    #pragma unroll
    for (int j = 0; j < 4; j++) {
        unsigned d = (unsigned)__cvta_generic_to_shared(dst + j * 128 + lane * 4);
        asm volatile("cp.async.cg.shared.global [%0], [%1], 16;\n"
                     :: "r"(d), "l"(src + j * 128 + lane * 4));
    }
    asm volatile("cp.async.commit_group;\n" ::: "memory");
}
template <int N> __device__ __forceinline__ void cp_wait() {
    asm volatile("cp.async.wait_group %0;\n" :: "n"(N) : "memory");
}

// ---------- single fused kernel ----------
// grid (NTILES, BB, NGROUP) = 1760 blocks, 288 threads, 3 blocks/SM (60KB dyn smem)
__global__ void __launch_bounds__(THREADS, 3)
fused_kernel(const float* __restrict__ X,
             const float* __restrict__ Y,
             const float* __restrict__ Mk,
             float* __restrict__ out) {
    extern __shared__ __align__(16) float smem[];
    float* tile = smem;                    // [6][TILE]
    float* ring = smem + SMEM_TILE_F;      // [NWARP][2][CHUNK]
    __shared__ unsigned int s_last;

    const int b    = blockIdx.y;
    const int t0   = blockIdx.x * TILE;
    const int g    = blockIdx.z;
    const int tid  = threadIdx.x;
    const int warp = tid >> 5;
    const int lane = tid & 31;

    // --- issue this warp's mask chunk loads FIRST (fire-and-forget) ---
    const int sm = g * SMG + warp;         // exactly one (s,m) task per warp
    const float* msrc = Mk + (size_t)(b * SMN + sm) * (size_t)HW + t0;
    float* myring = ring + warp * (2 * CHUNK);
    cp_chunk(myring,         msrc,         lane);
    cp_chunk(myring + CHUNK, msrc + CHUNK, lane);

    // --- fill tile with rescaled X', Y' (1536 float4 over 288 threads) ---
    const float4* X4 = (const float4*)X;
    const float4* Y4 = (const float4*)Y;
    #pragma unroll
    for (int r = 0; r < 6; r++) {
        int idx = r * THREADS + tid;
        if (idx < 6 * (TILE / 4)) {
            int ch  = idx >> 8;            // /256
            int pos = idx & 255;
            float4 v = (ch < 3) ? X4[((b * 3 + ch) * HW + t0) / 4 + pos]
                                : Y4[((b * 3 + (ch - 3)) * HW + t0) / 4 + pos];
            v.x = fmaf(v.x, 0.5f, 0.5f);
            v.y = fmaf(v.y, 0.5f, 0.5f);
            v.z = fmaf(v.z, 0.5f, 0.5f);
            v.w = fmaf(v.w, 0.5f, 0.5f);
            *(float4*)&tile[ch * TILE + pos * 4] = v;
        }
    }
    __syncthreads();

    // --- accumulate moments for this warp's (s,m) over the 1024-elem tile ---
    // acc[0]=mask sum; acc[1+c*5+{0..4}] = {mx, my, mxx, myy, mxy} per channel
    unsigned long long acc[NCOMP];
    #pragma unroll
    for (int k = 0; k < NCOMP; k++) acc[k] = 0ULL;

    #pragma unroll
    for (int q = 0; q < NCHUNK; q++) {
        if (q == 0) cp_wait<1>(); else cp_wait<0>();
        const float4* m4 = (const float4*)(myring + q * CHUNK);
        const int cbase = q * CHUNK;

        #pragma unroll
        for (int i = 0; i < CHUNK4 / 32; i++) {   // 4 float4 iterations
            float4 m = m4[i * 32 + lane];
            unsigned long long m01 = pk2(m.x, m.y);
            unsigned long long m23 = pk2(m.z, m.w);
            acc[0] = add2(acc[0], m01);
            acc[0] = add2(acc[0], m23);

            #pragma unroll
            for (int c = 0; c < 3; c++) {
                float4 x = *(const float4*)&tile[c * TILE + cbase + (i * 32 + lane) * 4];
                float4 y = *(const float4*)&tile[(3 + c) * TILE + cbase + (i * 32 + lane) * 4];
                unsigned long long x01 = pk2(x.x, x.y), x23 = pk2(x.z, x.w);
                unsigned long long y01 = pk2(y.x, y.y), y23 = pk2(y.z, y.w);

                unsigned long long mx01 = mul2(m01, x01);
                unsigned long long my01 = mul2(m01, y01);
                unsigned long long mx23 = mul2(m23, x23);
                unsigned long long my23 = mul2(m23, y23);

                const int o = 1 + c * 5;
                acc[o + 0] = add2(acc[o + 0], mx01);
                acc[o + 0] = add2(acc[o + 0], mx23);
                acc[o + 1] = add2(acc[o + 1], my01);
                acc[o + 1] = add2(acc[o + 1], my23);
                acc[o + 2] = fma2(mx01, x01, acc[o + 2]);
                acc[o + 2] = fma2(mx23, x23, acc[o + 2]);
                acc[o + 3] = fma2(my01, y01, acc[o + 3]);
                acc[o + 3] = fma2(my23, y23, acc[o + 3]);
                acc[o + 4] = fma2(mx01, y01, acc[o + 4]);
                acc[o + 4] = fma2(mx23, y23, acc[o + 4]);
            }
        }
    }

    // collapse f32x2 halves; 2-level butterfly; lanes 0-7 commit partials
    {
        float v[NCOMP];
        #pragma unroll
        for (int k = 0; k < NCOMP; k++) {
            float lo, hi;
            upk2(acc[k], lo, hi);
            v[k] = lo + hi;
        }
        #pragma unroll
        for (int off = 16; off >= 8; off >>= 1) {
            #pragma unroll
            for (int k = 0; k < NCOMP; k++)
                v[k] += __shfl_xor_sync(0xffffffffu, v[k], off);
        }
        if (lane < 8) {
            float* p = &g_part[(b * SMN + sm) * NCOMP];
            #pragma unroll
            for (int k = 0; k < NCOMP; k++) atomicAdd(p + k, v[k]);
        }
        __threadfence();   // make this warp's partials globally visible
    }

    // ---------------- last-block finalize ----------------
    __syncthreads();
    if (tid == 0) {
        unsigned int r = atomicAdd(&g_count, 1u);
        s_last = (r == TOTAL_BLOCKS - 1) ? 1u : 0u;
    }
    __syncthreads();
    if (!s_last) return;

    __threadfence();   // acquire-side ordering before reading g_part

    // reuse smem for the tiny epilogue accumulators
    float* csb = tile;          // [BB*SS] = 20
    float* ssb = tile + 32;     // [BB*SS]
    if (tid < BB * SS) { csb[tid] = 0.0f; ssb[tid] = 0.0f; }
    __syncthreads();

    for (int idx = tid; idx < BB * SMN * CC; idx += THREADS) {
        int bb = idx / (SMN * CC);
        int r2 = idx % (SMN * CC);
        int s  = r2 / (MM * CC);
        int mc = r2 % (MM * CC);
        int m  = mc / CC;
        int c  = mc % CC;
        const float* p = &g_part[(bb * SMN + s * MM + m) * NCOMP];
        float inv  = __fdividef(1.0f, p[0] + EPSF);
        float mu1  = p[1 + c * 5 + 0] * inv;
        float mu2  = p[1 + c * 5 + 1] * inv;
        float mu11 = p[1 + c * 5 + 2] * inv;
        float mu22 = p[1 + c * 5 + 3] * inv;
        float mu12 = p[1 + c * 5 + 4] * inv;
        float s1  = mu11 - mu1 * mu1;
        float s2  = mu22 - mu2 * mu2;
        float s12 = mu12 - mu1 * mu2;
        float cs   = __fdividef(2.0f * s12 + K2C, s1 + s2 + K2C);
        float ssim = __fdividef(2.0f * mu1 * mu2 + K1C, mu1 * mu1 + mu2 * mu2 + K1C) * cs;
        cs   = fmaxf(cs, 0.0f);
        ssim = fmaxf(ssim, 0.0f);
        atomicAdd(&csb[bb * SS + s], cs);
        atomicAdd(&ssb[bb * SS + s], ssim);
    }
    __syncthreads();

    // re-zero partials + counter for the next invocation / graph replay
    for (int i = tid; i < BB * SMN * NCOMP; i += THREADS) g_part[i] = 0.0f;
    if (tid == 1) g_count = 0u;

    if (tid == 0) {
        const float invMC = 1.0f / (float)(MM * CC);
        float accb = 0.0f;
        #pragma unroll
        for (int bb = 0; bb < BB; bb++) {
            float prod = ssb[bb * SS + (SS - 1)] * invMC;
            #pragma unroll
            for (int s = 0; s < SS - 1; s++) prod *= csb[bb * SS + s] * invMC;
            accb += prod;
        }
        out[0] = accb / (float)BB;
    }
}

extern "C" void kernel_launch(void* const* d_in, const int* in_sizes, int n_in,
                              void* d_out, int out_size) {
    const float* X  = (const float*)d_in[0];
    const float* Y  = (const float*)d_in[1];
    const float* Mk = (const float*)d_in[2];
    float* out = (float*)d_out;

    cudaFuncSetAttribute(fused_kernel,
                         cudaFuncAttributeMaxDynamicSharedMemorySize, SMEM_TOTAL_B);
    dim3 grid(NTILES, BB, NGROUP);
    fused_kernel<<<grid, THREADS, SMEM_TOTAL_B>>>(X, Y, Mk, out);
}

// round 11
// speedup vs baseline: 2.5215x; 2.5215x over previous
#include <cuda_runtime.h>
#include <cuda_bf16.h>

// Problem constants
#define BB 4
#define CC 3
#define HW 45056          // 256*176 = 88*512
#define SS 5
#define MM 18
#define SMN (SS*MM)       // 90
#define TILE 512          // hw scalars per block tile
#define NTILES (HW/TILE)  // 88
#define NGROUP 5
#define SMG (SMN/NGROUP)  // 18 tasks per block
#define NWARP 6
#define THREADS (NWARP*32)        // 192
#define TPW (SMG/NWARP)           // 3 tasks per warp (exact)
#define CHUNK 256                 // floats per cp.async chunk (1KB)
#define CHUNK4 (CHUNK/4)          // 64 float4
#define NCHT 2                    // chunks per task
#define TOTQ (TPW*NCHT)           // 6 chunks per warp
#define NCOMP 16                  // 1 mask sum + 3 channels * 5 moments
#define TOTAL_BLOCKS (NTILES*BB*NGROUP)   // 1760

#define SMEM_TILE_F (6*TILE)              // 3072 floats (12KB)
#define SMEM_RING_F (NWARP*2*CHUNK)       // 3072 floats (12KB)
#define SMEM_TOTAL_B ((SMEM_TILE_F + SMEM_RING_F)*4)   // 24576 B

#define K1C 0.0001f       // (0.01)^2
#define K2C 0.0009f       // (0.03)^2
#define EPSF 1e-6f

// zero at module load; finalizing block re-zeroes after use so every
// kernel_launch / graph replay starts from zeros.
__device__ float g_part[BB * SMN * NCOMP];
__device__ unsigned int g_count;

// ---------- f32x2 packed math helpers (sm_103a) ----------
__device__ __forceinline__ unsigned long long pk2(float lo, float hi) {
    unsigned long long r;
    asm("mov.b64 %0, {%1, %2};" : "=l"(r) : "f"(lo), "f"(hi));
    return r;
}
__device__ __forceinline__ void upk2(unsigned long long v, float& lo, float& hi) {
    asm("mov.b64 {%0, %1}, %2;" : "=f"(lo), "=f"(hi) : "l"(v));
}
__device__ __forceinline__ unsigned long long mul2(unsigned long long a, unsigned long long b) {
    unsigned long long r;
    asm("mul.rn.f32x2 %0, %1, %2;" : "=l"(r) : "l"(a), "l"(b));
    return r;
}
__device__ __forceinline__ unsigned long long add2(unsigned long long a, unsigned long long b) {
    unsigned long long r;
    asm("add.rn.f32x2 %0, %1, %2;" : "=l"(r) : "l"(a), "l"(b));
    return r;
}
__device__ __forceinline__ unsigned long long fma2(unsigned long long a, unsigned long long b,
                                                   unsigned long long c) {
    unsigned long long r;
    asm("fma.rn.f32x2 %0, %1, %2, %3;" : "=l"(r) : "l"(a), "l"(b), "l"(c));
    return r;
}

// ---------- cp.async helpers ----------
// Copy one CHUNK (256 floats = 1KB) warp-collectively: 2 x 16B per lane.
// Producer lane == consumer lane for each float4 (index j*32+lane), so no
// cross-lane sync needed after cp.async.wait_group.
__device__ __forceinline__ void cp_chunk(float* dst, const float* src, int lane) {
    #pragma unroll
    for (int j = 0; j < 2; j++) {
        unsigned d = (unsigned)__cvta_generic_to_shared(dst + (j * 32 + lane) * 4);
        asm volatile("cp.async.cg.shared.global [%0], [%1], 16;\n"
                     :: "r"(d), "l"(src + (j * 32 + lane) * 4));
    }
    asm volatile("cp.async.commit_group;\n" ::: "memory");
}
template <int N> __device__ __forceinline__ void cp_wait() {
    asm volatile("cp.async.wait_group %0;\n" :: "n"(N) : "memory");
}

// ---------- single fused kernel ----------
// grid (NTILES, BB, NGROUP) = 1760 blocks, 192 threads, 5 blocks/SM
__global__ void __launch_bounds__(THREADS, 5)
fused_kernel(const float* __restrict__ X,
             const float* __restrict__ Y,
             const float* __restrict__ Mk,
             float* __restrict__ out) {
    extern __shared__ __align__(16) float smem[];
    float* tile = smem;                    // [6][TILE]
    float* ring = smem + SMEM_TILE_F;      // [NWARP][2][CHUNK]
    __shared__ unsigned int s_last;

    const int b    = blockIdx.y;
    const int t0   = blockIdx.x * TILE;
    const int g    = blockIdx.z;
    const int tid  = threadIdx.x;
    const int warp = tid >> 5;
    const int lane = tid & 31;

    // warp's 3 consecutive (s,m) tasks; chunk q covers task q/2, half q%2
    const int sm0 = g * SMG + warp * TPW;
    const float* mbase = Mk + (size_t)(b * SMN + sm0) * (size_t)HW + t0;
    float* myring = ring + warp * (2 * CHUNK);

    // --- prologue: 2 chunks in flight before anything else ---
    cp_chunk(myring,         mbase,         lane);                 // q=0
    cp_chunk(myring + CHUNK, mbase + CHUNK, lane);                 // q=1

    // --- fill tile with rescaled X', Y' (768 float4 over 192 threads) ---
    const float4* X4 = (const float4*)X;
    const float4* Y4 = (const float4*)Y;
    #pragma unroll
    for (int r = 0; r < 4; r++) {
        int idx = r * THREADS + tid;       // 0..767
        int ch  = idx >> 7;                // /128
        int pos = idx & 127;
        float4 v = (ch < 3) ? X4[((b * 3 + ch) * HW + t0) / 4 + pos]
                            : Y4[((b * 3 + (ch - 3)) * HW + t0) / 4 + pos];
        v.x = fmaf(v.x, 0.5f, 0.5f);
        v.y = fmaf(v.y, 0.5f, 0.5f);
        v.z = fmaf(v.z, 0.5f, 0.5f);
        v.w = fmaf(v.w, 0.5f, 0.5f);
        *(float4*)&tile[ch * TILE + pos * 4] = v;
    }
    __syncthreads();

    // acc[0]=mask sum; acc[1+c*5+{0..4}] = {mx, my, mxx, myy, mxy} per channel
    unsigned long long acc[NCOMP];
    #pragma unroll
    for (int k = 0; k < NCOMP; k++) acc[k] = 0ULL;

    // --- pipelined chunk loop: compute q while q+1 in flight; issue q+2 ---
    #pragma unroll
    for (int q = 0; q < TOTQ; q++) {
        if (q == TOTQ - 1) cp_wait<0>(); else cp_wait<1>();

        const int slot = q & 1;
        const float4* m4 = (const float4*)(myring + slot * CHUNK);
        const int cbase = (q & 1) * CHUNK;     // tile offset for this half

        #pragma unroll
        for (int i = 0; i < CHUNK4 / 32; i++) {   // 2 float4 iterations
            float4 m = m4[i * 32 + lane];
            unsigned long long m01 = pk2(m.x, m.y);
            unsigned long long m23 = pk2(m.z, m.w);
            acc[0] = add2(acc[0], m01);
            acc[0] = add2(acc[0], m23);

            #pragma unroll
            for (int c = 0; c < 3; c++) {
                float4 x = *(const float4*)&tile[c * TILE + cbase + (i * 32 + lane) * 4];
                float4 y = *(const float4*)&tile[(3 + c) * TILE + cbase + (i * 32 + lane) * 4];
                unsigned long long x01 = pk2(x.x, x.y), x23 = pk2(x.z, x.w);
                unsigned long long y01 = pk2(y.x, y.y), y23 = pk2(y.z, y.w);

                unsigned long long mx01 = mul2(m01, x01);
                unsigned long long my01 = mul2(m01, y01);
                unsigned long long mx23 = mul2(m23, x23);
                unsigned long long my23 = mul2(m23, y23);

                const int o = 1 + c * 5;
                acc[o + 0] = add2(acc[o + 0], mx01);
                acc[o + 0] = add2(acc[o + 0], mx23);
                acc[o + 1] = add2(acc[o + 1], my01);
                acc[o + 1] = add2(acc[o + 1], my23);
                acc[o + 2] = fma2(mx01, x01, acc[o + 2]);
                acc[o + 2] = fma2(mx23, x23, acc[o + 2]);
                acc[o + 3] = fma2(my01, y01, acc[o + 3]);
                acc[o + 3] = fma2(my23, y23, acc[o + 3]);
                acc[o + 4] = fma2(mx01, y01, acc[o + 4]);
                acc[o + 4] = fma2(mx23, y23, acc[o + 4]);
            }
        }

        // refill the slot we just consumed with chunk q+2 (crosses task bounds)
        if (q + 2 < TOTQ)
            cp_chunk(myring + slot * CHUNK,
                     mbase + (size_t)((q + 2) >> 1) * (size_t)HW + ((q + 2) & 1) * CHUNK,
                     lane);

        // end of a task: butterfly-reduce across warp, lane 0 commits, reset acc
        if (q & 1) {
            const int sm = sm0 + (q >> 1);
            float* p = &g_part[(b * SMN + sm) * NCOMP];
            float v[NCOMP];
            #pragma unroll
            for (int k = 0; k < NCOMP; k++) {
                float lo, hi;
                upk2(acc[k], lo, hi);
                v[k] = lo + hi;
                acc[k] = 0ULL;
            }
            #pragma unroll
            for (int off = 16; off > 0; off >>= 1) {
                #pragma unroll
                for (int k = 0; k < NCOMP; k++)
                    v[k] += __shfl_xor_sync(0xffffffffu, v[k], off);
            }
            if (lane == 0) {
                #pragma unroll
                for (int k = 0; k < NCOMP; k++) atomicAdd(p + k, v[k]);
            }
        }
    }

    // ---------------- last-block finalize (R8-validated pattern) ----------------
    __syncthreads();   // all warps in this block have issued their g_part atomics
    if (tid == 0) {
        __threadfence();                               // make our atomics visible
        unsigned int r = atomicAdd(&g_count, 1u);
        s_last = (r == TOTAL_BLOCKS - 1) ? 1u : 0u;
    }
    __syncthreads();
    if (!s_last) return;

    __threadfence();   // acquire-side ordering before reading g_part

    // reuse smem for the tiny epilogue accumulators
    float* csb = tile;          // [BB*SS] = 20
    float* ssb = tile + 32;
    if (tid < BB * SS) { csb[tid] = 0.0f; ssb[tid] = 0.0f; }
    __syncthreads();

    for (int idx = tid; idx < BB * SMN * CC; idx += THREADS) {
        int bb = idx / (SMN * CC);
        int r2 = idx % (SMN * CC);
        int s  = r2 / (MM * CC);
        int mc = r2 % (MM * CC);
        int m  = mc / CC;
        int c  = mc % CC;
        const float* p = &g_part[(bb * SMN + s * MM + m) * NCOMP];
        float inv  = __fdividef(1.0f, p[0] + EPSF);
        float mu1  = p[1 + c * 5 + 0] * inv;
        float mu2  = p[1 + c * 5 + 1] * inv;
        float mu11 = p[1 + c * 5 + 2] * inv;
        float mu22 = p[1 + c * 5 + 3] * inv;
        float mu12 = p[1 + c * 5 + 4] * inv;
        float s1  = mu11 - mu1 * mu1;
        float s2  = mu22 - mu2 * mu2;
        float s12 = mu12 - mu1 * mu2;
        float cs   = __fdividef(2.0f * s12 + K2C, s1 + s2 + K2C);
        float ssim = __fdividef(2.0f * mu1 * mu2 + K1C, mu1 * mu1 + mu2 * mu2 + K1C) * cs;
        cs   = fmaxf(cs, 0.0f);
        ssim = fmaxf(ssim, 0.0f);
        atomicAdd(&csb[bb * SS + s], cs);
        atomicAdd(&ssb[bb * SS + s], ssim);
    }
    __syncthreads();

    // re-zero partials + counter for the next invocation / graph replay
    for (int i = tid; i < BB * SMN * NCOMP; i += THREADS) g_part[i] = 0.0f;
    if (tid == 1) g_count = 0u;

    if (tid == 0) {
        const float invMC = 1.0f / (float)(MM * CC);
        float accb = 0.0f;
        #pragma unroll
        for (int bb = 0; bb < BB; bb++) {
            float prod = ssb[bb * SS + (SS - 1)] * invMC;
            #pragma unroll
            for (int s = 0; s < SS - 1; s++) prod *= csb[bb * SS + s] * invMC;
            accb += prod;
        }
        out[0] = accb / (float)BB;
    }
}

extern "C" void kernel_launch(void* const* d_in, const int* in_sizes, int n_in,
                              void* d_out, int out_size) {
    const float* X  = (const float*)d_in[0];
    const float* Y  = (const float*)d_in[1];
    const float* Mk = (const float*)d_in[2];
    float* out = (float*)d_out;

    cudaFuncSetAttribute(fused_kernel,
                         cudaFuncAttributeMaxDynamicSharedMemorySize, SMEM_TOTAL_B);
    dim3 grid(NTILES, BB, NGROUP);
    fused_kernel<<<grid, THREADS, SMEM_TOTAL_B>>>(X, Y, Mk, out);
}